// round 7
// baseline (speedup 1.0000x reference)
#include <cuda_runtime.h>
#include <cuda_bf16.h>
#include <cstdint>
#include <math.h>

// Shapes (fixed)
#define Bsz 8
#define Sq  2048
#define Dd  512
#define Hh  512
#define MS  (Bsz * Sq)   // 16384

// ---------------- scratch (device globals) ----------------
__device__ __nv_bfloat16 g_xb  [(long)MS * Dd];
__device__ __nv_bfloat16 g_qb  [(long)MS * Hh];
__device__ __nv_bfloat16 g_kb  [(long)MS * Hh];
__device__ __nv_bfloat16 g_vTb [(long)MS * Hh];     // [Hh, MS]
__device__ __nv_bfloat16 g_ctxb[(long)MS * Hh];
__device__ __nv_bfloat16 g_wqt[Dd * Hh];
__device__ __nv_bfloat16 g_wkt[Dd * Hh];
__device__ __nv_bfloat16 g_wvt[Dd * Hh];
__device__ __nv_bfloat16 g_wot[Dd * Hh];

// ---------------- helpers ----------------
__device__ __forceinline__ uint32_t smem_u32(const void* p) {
    uint32_t a;
    asm("{ .reg .u64 t; cvta.to.shared.u64 t, %1; cvt.u32.u64 %0, t; }" : "=r"(a) : "l"(p));
    return a;
}
#define LDSM4(r, a)                                                              \
    asm volatile("ldmatrix.sync.aligned.m8n8.x4.shared.b16 {%0,%1,%2,%3}, [%4];" \
                 : "=r"((r)[0]), "=r"((r)[1]), "=r"((r)[2]), "=r"((r)[3])        \
                 : "r"(a))
__device__ __forceinline__ void mma_bf16(float* c, const uint32_t* a,
                                         uint32_t b0, uint32_t b1) {
    asm volatile(
        "mma.sync.aligned.m16n8k16.row.col.f32.bf16.bf16.f32 "
        "{%0,%1,%2,%3}, {%4,%5,%6,%7}, {%8,%9}, {%0,%1,%2,%3};"
        : "+f"(c[0]), "+f"(c[1]), "+f"(c[2]), "+f"(c[3])
        : "r"(a[0]), "r"(a[1]), "r"(a[2]), "r"(a[3]), "r"(b0), "r"(b1));
}
#define CP_ASYNC(dst, src) \
    asm volatile("cp.async.cg.shared.global [%0], [%1], 16;" :: "r"(dst), "l"(src))
#define CP_COMMIT() asm volatile("cp.async.commit_group;" ::: "memory")
#define CP_WAIT(n)  asm volatile("cp.async.wait_group %0;" :: "n"(n) : "memory")

// ============================================================================
// bf16 NT GEMM (projections + out-proj) — unchanged from R5
// ============================================================================
#define RS 144
#define B_OFF  (128 * RS)
#define STAGE  (256 * RS)
#define NSTAGE 3
#define GSMEM_TOTAL (NSTAGE * STAGE)

__device__ __forceinline__ void stage_load(
    uint32_t sbase, const __nv_bfloat16* __restrict__ A, long lda,
    const __nv_bfloat16* __restrict__ B, long ldb, int m0, int n0, int kt, int t)
{
    const int lrow = t >> 3, lch = t & 7;
#pragma unroll
    for (int i = 0; i < 4; i++) {
        const int row = lrow + i * 32;
        CP_ASYNC(sbase + row * RS + lch * 16,
                 A + (long)(m0 + row) * lda + kt + lch * 8);
    }
#pragma unroll
    for (int i = 0; i < 4; i++) {
        const int row = lrow + i * 32;
        CP_ASYNC(sbase + B_OFF + row * RS + lch * 16,
                 B + (long)(n0 + row) * ldb + kt + lch * 8);
    }
}

__global__ __launch_bounds__(256, 2) void gemm_bf16_nt(
    const __nv_bfloat16* __restrict__ A, long lda, long sA,
    const __nv_bfloat16* __restrict__ B, long ldb, long sB,
    void* __restrict__ Cv, long ldc, long sC,
    const float* __restrict__ biasN, const float* __restrict__ biasM,
    const float* __restrict__ res, float alpha, int K, int c_bf16)
{
    extern __shared__ __align__(128) char smem[];
    const uint32_t sb = smem_u32(smem);
    const int t = threadIdx.x;
    const int m0 = blockIdx.x * 128;
    const int n0 = blockIdx.y * 128;

    A += (long)blockIdx.z * sA;
    B += (long)blockIdx.z * sB;
    const float* resz = res ? res + (long)blockIdx.z * sC : nullptr;

    const int lane = t & 31, w = t >> 5;
    const int wm = w & 1, wn = w >> 1;

    const uint32_t aB = sb + (wm * 64 + (lane & 15)) * RS + (lane >> 4) * 16;
    const uint32_t bB = sb + B_OFF + (wn * 32 + (lane & 15)) * RS + (lane >> 4) * 16;

    float acc[4][4][4];
#pragma unroll
    for (int i = 0; i < 4; i++)
#pragma unroll
        for (int j = 0; j < 4; j++)
#pragma unroll
            for (int r = 0; r < 4; r++) acc[i][j][r] = 0.f;

    const int ktiles = K / 64;
    stage_load(sb, A, lda, B, ldb, m0, n0, 0, t);
    CP_COMMIT();
    if (ktiles > 1) stage_load(sb + STAGE, A, lda, B, ldb, m0, n0, 64, t);
    CP_COMMIT();

    for (int kt = 0; kt < ktiles; kt++) {
        if (kt + 2 < ktiles)
            stage_load(sb + ((kt + 2) % NSTAGE) * STAGE, A, lda, B, ldb,
                       m0, n0, (kt + 2) * 64, t);
        CP_COMMIT();
        CP_WAIT(2);
        __syncthreads();

        const uint32_t so = (kt % NSTAGE) * STAGE;
#pragma unroll
        for (int s = 0; s < 4; s++) {
            uint32_t af[4][4], bf[2][4];
#pragma unroll
            for (int mt = 0; mt < 4; mt++)
                LDSM4(af[mt], aB + so + mt * (16 * RS) + s * 32);
#pragma unroll
            for (int p = 0; p < 2; p++)
                LDSM4(bf[p], bB + so + p * (16 * RS) + s * 32);
#pragma unroll
            for (int mt = 0; mt < 4; mt++)
#pragma unroll
                for (int p = 0; p < 2; p++) {
                    mma_bf16(acc[mt][2 * p + 0], af[mt], bf[p][0], bf[p][2]);
                    mma_bf16(acc[mt][2 * p + 1], af[mt], bf[p][1], bf[p][3]);
                }
        }
        __syncthreads();
    }

    const int gcol0 = (lane & 3) * 2;
    const int grow  = lane >> 2;
#pragma unroll
    for (int mt = 0; mt < 4; mt++) {
        const long row = m0 + wm * 64 + mt * 16 + grow;
        const float bm0 = biasM ? biasM[row] : 0.f;
        const float bm1 = biasM ? biasM[row + 8] : 0.f;
#pragma unroll
        for (int nt = 0; nt < 4; nt++) {
            const int col = n0 + wn * 32 + nt * 8 + gcol0;
            float2 v0, v1;
            v0.x = acc[mt][nt][0] * alpha + bm0;
            v0.y = acc[mt][nt][1] * alpha + bm0;
            v1.x = acc[mt][nt][2] * alpha + bm1;
            v1.y = acc[mt][nt][3] * alpha + bm1;
            if (biasN) {
                const float2 bb = *(const float2*)(biasN + col);
                v0.x += bb.x; v0.y += bb.y; v1.x += bb.x; v1.y += bb.y;
            }
            if (resz) {
                const float2 r0 = *(const float2*)(resz + row * ldc + col);
                const float2 r1 = *(const float2*)(resz + (row + 8) * ldc + col);
                v0.x += r0.x; v0.y += r0.y; v1.x += r1.x; v1.y += r1.y;
            }
            if (c_bf16) {
                __nv_bfloat16* C = (__nv_bfloat16*)Cv + (long)blockIdx.z * sC;
                *(__nv_bfloat162*)(C + row * ldc + col) = __float22bfloat162_rn(v0);
                *(__nv_bfloat162*)(C + (row + 8) * ldc + col) = __float22bfloat162_rn(v1);
            } else {
                float* C = (float*)Cv + (long)blockIdx.z * sC;
                *(float2*)(C + row * ldc + col) = v0;
                *(float2*)(C + (row + 8) * ldc + col) = v1;
            }
        }
    }
}

// ============================================================================
// Flash attention: ctx = softmax(Q K^T * alpha) @ V, fused.
// Grid (Sq/64, Bsz), 512 threads (16 warps: 2 m-groups x 8 slices).
// ============================================================================
#define QB 64
#define TKV 128
#define NT (Sq / TKV)        // 16
#define QS_STRIDE 1040
#define K_STRIDE 144
#define V_STRIDE 144
#define P_STRIDE 272
#define QS_OFF 0
#define KB_OFF (QB * QS_STRIDE)                  // 66560
#define KCH_BYTES (TKV * K_STRIDE)               // 18432
#define VB_OFF (KB_OFF + 3 * KCH_BYTES)          // 121856
#define VB_BYTES (512 * V_STRIDE)                // 73728
#define PS_OFF (VB_OFF + VB_BYTES)               // 195584
#define REDM_OFF (PS_OFF + QB * P_STRIDE)        // 212992
#define REDS_OFF (REDM_OFF + QB * 9 * 4)         // 215296
#define FA_SMEM (REDS_OFF + QB * 9 * 4)          // 217600

__global__ __launch_bounds__(512, 1) void flash_attn(
    const __nv_bfloat16* __restrict__ Qg,
    const __nv_bfloat16* __restrict__ Kg,
    const __nv_bfloat16* __restrict__ Vtg,
    __nv_bfloat16* __restrict__ Og, float alpha)
{
    extern __shared__ __align__(128) char smem[];
    const uint32_t sb = smem_u32(smem);
    const int t = threadIdx.x;
    const int lane = t & 31, w = t >> 5;
    const int mg = w >> 3, ws = w & 7;
    const int batch = blockIdx.y;
    const long q0 = (long)blockIdx.x * QB;

    const __nv_bfloat16* qptr = Qg + ((long)batch * Sq + q0) * Hh;
    const __nv_bfloat16* kptr = Kg + (long)batch * Sq * Hh;
    const __nv_bfloat16* vptr = Vtg + (long)batch * Sq;

    const int krow = t >> 2, kch = t & 3;

    // Each K chunk / V group = 128 rows x 128 B. 512 threads x 2 x 16 B covers it.
#define LOAD_K(tile_, chunk_, buf_) do {                                           \
        const uint32_t d_ = sb + KB_OFF + (buf_) * KCH_BYTES + krow * K_STRIDE + kch * 16; \
        const __nv_bfloat16* s_ = kptr + ((long)(tile_) * TKV + krow) * Hh + (chunk_) * 64 + kch * 8; \
        CP_ASYNC(d_, s_);                                                          \
        CP_ASYNC(d_ + 64, s_ + 32);                                                \
        CP_COMMIT(); } while (0)
#define LOAD_V(tile_, half_, grp_) do {                                            \
        const int vr_ = (grp_) * 128 + krow;                                       \
        const uint32_t d_ = sb + VB_OFF + vr_ * V_STRIDE + kch * 16;               \
        const __nv_bfloat16* s_ = vptr + (long)vr_ * MS + (tile_) * TKV + (half_) * 64 + kch * 8; \
        CP_ASYNC(d_, s_);                                                          \
        CP_ASYNC(d_ + 64, s_ + 32);                                                \
        CP_COMMIT(); } while (0)

    // Q load (1 group): 64 rows x 1024 B
    {
        const int row = t >> 3, ch = t & 7;
#pragma unroll
        for (int j = 0; j < 8; j++)
            CP_ASYNC(sb + QS_OFF + row * QS_STRIDE + (ch + j * 8) * 16,
                     qptr + (long)row * Hh + (ch + j * 8) * 8);
        CP_COMMIT();
    }
    LOAD_K(0, 0, 0);
    LOAD_K(0, 1, 1);

    float acc[2][8][4];
#pragma unroll
    for (int i = 0; i < 2; i++)
#pragma unroll
        for (int j = 0; j < 8; j++)
#pragma unroll
            for (int r = 0; r < 4; r++) acc[i][j][r] = 0.f;
    float mrun[2][2], lrun[2][2];
#pragma unroll
    for (int i = 0; i < 2; i++)
#pragma unroll
        for (int j = 0; j < 2; j++) { mrun[i][j] = -1e30f; lrun[i][j] = 0.f; }

    const int fr = lane & 15, kh = lane >> 4;
    const uint32_t qA = sb + QS_OFF + (mg * 32 + fr) * QS_STRIDE + kh * 16;
    const uint32_t kB = sb + KB_OFF + (ws * 16 + fr) * K_STRIDE + kh * 16;
    const uint32_t pA = sb + PS_OFF + (mg * 32 + fr) * P_STRIDE + kh * 16;
    const uint32_t vB = sb + VB_OFF + (ws * 64 + fr) * V_STRIDE + kh * 16;
    const int grow = lane >> 2, gcol = (lane & 3) * 2;
    float* redm = (float*)(smem + REDM_OFF);
    float* reds = (float*)(smem + REDS_OFF);

    for (int tile = 0; tile < NT; tile++) {
        LOAD_K(tile, 2, 2);

        float s[2][2][4];
#pragma unroll
        for (int i = 0; i < 2; i++)
#pragma unroll
            for (int j = 0; j < 2; j++)
#pragma unroll
                for (int r = 0; r < 4; r++) s[i][j][r] = 0.f;

        // ---- QK^T over 8 chunks of 64 dims, 3-deep K pipeline ----
#pragma unroll
        for (int c = 0; c < 8; c++) {
            switch (c) {
                case 0: CP_WAIT(2); break;
                case 1: CP_WAIT(3); break;
                case 2: CP_WAIT(3); break;
                case 3: CP_WAIT(4); break;
                case 4: CP_WAIT(4); break;
                case 5: CP_WAIT(3); break;
                case 6: CP_WAIT(1); break;
                default:
                    if (tile + 1 < NT) { CP_WAIT(1); } else { CP_WAIT(0); }
                    break;
            }
            __syncthreads();
            {
                const uint32_t kb = kB + (c % 3) * KCH_BYTES;
#pragma unroll
                for (int ks = 0; ks < 4; ks++) {
                    uint32_t af0[4], af1[4], bf[4];
                    LDSM4(af0, qA + c * 128 + ks * 32);
                    LDSM4(af1, qA + 16 * QS_STRIDE + c * 128 + ks * 32);
                    LDSM4(bf, kb + ks * 32);
                    mma_bf16(s[0][0], af0, bf[0], bf[2]);
                    mma_bf16(s[0][1], af0, bf[1], bf[3]);
                    mma_bf16(s[1][0], af1, bf[0], bf[2]);
                    mma_bf16(s[1][1], af1, bf[1], bf[3]);
                }
            }
            __syncthreads();
            if (c < 4) LOAD_V(tile, 0, c);
            if (c < 5) LOAD_K(tile, c + 3, c % 3);
            if (c == 6 && tile + 1 < NT) LOAD_K(tile + 1, 0, 0);
            if (c == 7 && tile + 1 < NT) LOAD_K(tile + 1, 1, 1);
        }

        // ---- online softmax ----
#pragma unroll
        for (int i = 0; i < 2; i++)
#pragma unroll
            for (int j = 0; j < 2; j++)
#pragma unroll
                for (int r = 0; r < 4; r++) s[i][j][r] *= alpha;

        float lm[2][2];
#pragma unroll
        for (int mf = 0; mf < 2; mf++)
#pragma unroll
            for (int hh = 0; hh < 2; hh++)
                lm[mf][hh] = fmaxf(fmaxf(s[mf][0][2 * hh], s[mf][0][2 * hh + 1]),
                                   fmaxf(s[mf][1][2 * hh], s[mf][1][2 * hh + 1]));
#pragma unroll
        for (int off = 1; off <= 2; off <<= 1)
#pragma unroll
            for (int mf = 0; mf < 2; mf++)
#pragma unroll
                for (int hh = 0; hh < 2; hh++)
                    lm[mf][hh] = fmaxf(lm[mf][hh],
                                       __shfl_xor_sync(0xffffffffu, lm[mf][hh], off));
        if ((lane & 3) == 0) {
#pragma unroll
            for (int mf = 0; mf < 2; mf++)
#pragma unroll
                for (int hh = 0; hh < 2; hh++) {
                    const int row = mg * 32 + mf * 16 + grow + hh * 8;
                    redm[row * 9 + ws] = lm[mf][hh];
                }
        }
        __syncthreads();

        float resc[2][2];
#pragma unroll
        for (int mf = 0; mf < 2; mf++)
#pragma unroll
            for (int hh = 0; hh < 2; hh++) {
                const int row = mg * 32 + mf * 16 + grow + hh * 8;
                float tm = redm[row * 9];
#pragma unroll
                for (int j = 1; j < 8; j++) tm = fmaxf(tm, redm[row * 9 + j]);
                const float mnew = fmaxf(mrun[mf][hh], tm);
                resc[mf][hh] = __expf(mrun[mf][hh] - mnew);
                mrun[mf][hh] = mnew;
                lrun[mf][hh] *= resc[mf][hh];
            }
#pragma unroll
        for (int mf = 0; mf < 2; mf++)
#pragma unroll
            for (int nf = 0; nf < 8; nf++)
#pragma unroll
                for (int r = 0; r < 4; r++)
                    acc[mf][nf][r] *= resc[mf][r >> 1];

        float ls[2][2] = {{0.f, 0.f}, {0.f, 0.f}};
#pragma unroll
        for (int mf = 0; mf < 2; mf++)
#pragma unroll
            for (int nf = 0; nf < 2; nf++) {
                const float e0 = __expf(s[mf][nf][0] - mrun[mf][0]);
                const float e1 = __expf(s[mf][nf][1] - mrun[mf][0]);
                const float e2 = __expf(s[mf][nf][2] - mrun[mf][1]);
                const float e3 = __expf(s[mf][nf][3] - mrun[mf][1]);
                ls[mf][0] += e0 + e1;
                ls[mf][1] += e2 + e3;
                const int col = ws * 16 + nf * 8 + gcol;
                const int row = mg * 32 + mf * 16 + grow;
                *(__nv_bfloat162*)(smem + PS_OFF + row * P_STRIDE + col * 2) =
                    __float22bfloat162_rn(make_float2(e0, e1));
                *(__nv_bfloat162*)(smem + PS_OFF + (row + 8) * P_STRIDE + col * 2) =
                    __float22bfloat162_rn(make_float2(e2, e3));
            }
#pragma unroll
        for (int off = 1; off <= 2; off <<= 1)
#pragma unroll
            for (int mf = 0; mf < 2; mf++)
#pragma unroll
                for (int hh = 0; hh < 2; hh++)
                    ls[mf][hh] += __shfl_xor_sync(0xffffffffu, ls[mf][hh], off);
        if ((lane & 3) == 0) {
#pragma unroll
            for (int mf = 0; mf < 2; mf++)
#pragma unroll
                for (int hh = 0; hh < 2; hh++) {
                    const int row = mg * 32 + mf * 16 + grow + hh * 8;
                    reds[row * 9 + ws] = ls[mf][hh];
                }
        }
        __syncthreads();
#pragma unroll
        for (int mf = 0; mf < 2; mf++)
#pragma unroll
            for (int hh = 0; hh < 2; hh++) {
                const int row = mg * 32 + mf * 16 + grow + hh * 8;
                float ts = reds[row * 9];
#pragma unroll
                for (int j = 1; j < 8; j++) ts += reds[row * 9 + j];
                lrun[mf][hh] += ts;
            }

        // ---- PV: two halves of 64 keys ----
#pragma unroll
        for (int h = 0; h < 2; h++) {
            if (h == 1) {
                __syncthreads();
                LOAD_V(tile, 1, 0);
                LOAD_V(tile, 1, 1);
                LOAD_V(tile, 1, 2);
                LOAD_V(tile, 1, 3);
                CP_WAIT(0);
                __syncthreads();
            }
#pragma unroll
            for (int ks = 0; ks < 4; ks++) {
                uint32_t pf0[4], pf1[4], vf[4][4];
                LDSM4(pf0, pA + h * 128 + ks * 32);
                LDSM4(pf1, pA + 16 * P_STRIDE + h * 128 + ks * 32);
#pragma unroll
                for (int n = 0; n < 4; n++)
                    LDSM4(vf[n], vB + n * 16 * V_STRIDE + ks * 32);
#pragma unroll
                for (int n = 0; n < 4; n++) {
                    mma_bf16(acc[0][2 * n],     pf0, vf[n][0], vf[n][2]);
                    mma_bf16(acc[0][2 * n + 1], pf0, vf[n][1], vf[n][3]);
                    mma_bf16(acc[1][2 * n],     pf1, vf[n][0], vf[n][2]);
                    mma_bf16(acc[1][2 * n + 1], pf1, vf[n][1], vf[n][3]);
                }
            }
        }
    }

    // ---- epilogue ----
    float inv[2][2];
#pragma unroll
    for (int mf = 0; mf < 2; mf++)
#pragma unroll
        for (int hh = 0; hh < 2; hh++) inv[mf][hh] = 1.f / lrun[mf][hh];
#pragma unroll
    for (int mf = 0; mf < 2; mf++) {
        const long row = (long)batch * Sq + q0 + mg * 32 + mf * 16 + grow;
#pragma unroll
        for (int nf = 0; nf < 8; nf++) {
            const int col = ws * 64 + nf * 8 + gcol;
            *(__nv_bfloat162*)(Og + row * Hh + col) = __float22bfloat162_rn(
                make_float2(acc[mf][nf][0] * inv[mf][0], acc[mf][nf][1] * inv[mf][0]));
            *(__nv_bfloat162*)(Og + (row + 8) * Hh + col) = __float22bfloat162_rn(
                make_float2(acc[mf][nf][2] * inv[mf][1], acc[mf][nf][3] * inv[mf][1]));
        }
    }
#undef LOAD_K
#undef LOAD_V
}

// ---------------- 512x512 transpose -> bf16 ----------------
__global__ __launch_bounds__(256) void transpose512(const float* __restrict__ W,
                                                    __nv_bfloat16* __restrict__ Wt)
{
    __shared__ float tile[32][33];
    const int tx = threadIdx.x, ty = threadIdx.y;
    int x = blockIdx.x * 32 + tx;
    int y = blockIdx.y * 32 + ty;
#pragma unroll
    for (int i = 0; i < 4; i++)
        tile[ty + i * 8][tx] = W[(y + i * 8) * 512 + x];
    __syncthreads();
    x = blockIdx.y * 32 + tx;
    y = blockIdx.x * 32 + ty;
#pragma unroll
    for (int i = 0; i < 4; i++)
        Wt[(y + i * 8) * 512 + x] = __float2bfloat16_rn(tile[tx][ty + i * 8]);
}

// ---------------- fp32 -> bf16 bulk convert ----------------
__global__ __launch_bounds__(256) void cvt_bf16(const float* __restrict__ in,
                                                __nv_bfloat16* __restrict__ out, long n4)
{
    const long i = (long)blockIdx.x * blockDim.x + threadIdx.x;
    if (i < n4) {
        float4 v = ((const float4*)in)[i];
        *(__nv_bfloat162*)(out + i * 4)     = __float22bfloat162_rn(make_float2(v.x, v.y));
        *(__nv_bfloat162*)(out + i * 4 + 2) = __float22bfloat162_rn(make_float2(v.z, v.w));
    }
}

// ---------------- launch ----------------
extern "C" void kernel_launch(void* const* d_in, const int* in_sizes, int n_in,
                              void* d_out, int out_size)
{
    const float* x  = (const float*)d_in[0];
    const float* Wq = (const float*)d_in[1];
    const float* bq = (const float*)d_in[2];
    const float* Wk = (const float*)d_in[3];
    const float* bk = (const float*)d_in[4];
    const float* Wv = (const float*)d_in[5];
    const float* bv = (const float*)d_in[6];
    const float* Wo = (const float*)d_in[7];
    const float* bo = (const float*)d_in[8];
    float* out = (float*)d_out;

    __nv_bfloat16 *xb, *qb, *kb, *vTb, *ctxb, *wqt, *wkt, *wvt, *wot;
    cudaGetSymbolAddress((void**)&xb,   g_xb);
    cudaGetSymbolAddress((void**)&qb,   g_qb);
    cudaGetSymbolAddress((void**)&kb,   g_kb);
    cudaGetSymbolAddress((void**)&vTb,  g_vTb);
    cudaGetSymbolAddress((void**)&ctxb, g_ctxb);
    cudaGetSymbolAddress((void**)&wqt,  g_wqt);
    cudaGetSymbolAddress((void**)&wkt,  g_wkt);
    cudaGetSymbolAddress((void**)&wvt,  g_wvt);
    cudaGetSymbolAddress((void**)&wot,  g_wot);

    static int smem_set = 0;
    if (!smem_set) {
        cudaFuncSetAttribute(gemm_bf16_nt,
                             cudaFuncAttributeMaxDynamicSharedMemorySize, GSMEM_TOTAL);
        cudaFuncSetAttribute(flash_attn,
                             cudaFuncAttributeMaxDynamicSharedMemorySize, FA_SMEM);
        smem_set = 1;
    }

    // 0) transpose + convert weights; convert x
    {
        dim3 g(16, 16), b(32, 8);
        transpose512<<<g, b>>>(Wq, wqt);
        transpose512<<<g, b>>>(Wk, wkt);
        transpose512<<<g, b>>>(Wv, wvt);
        transpose512<<<g, b>>>(Wo, wot);
        const long n4 = (long)MS * Dd / 4;
        cvt_bf16<<<(n4 + 255) / 256, 256>>>(x, xb, n4);
    }

    const float inv_sqrt_h = 1.f / sqrtf((float)Hh);

    // 1) q = x @ Wq (+bq) -> bf16
    gemm_bf16_nt<<<dim3(MS / 128, Hh / 128, 1), 256, GSMEM_TOTAL>>>(
        xb, Dd, 0, wqt, Dd, 0, qb, Hh, 0, bq, nullptr, nullptr, 1.f, Dd, 1);
    // 2) k -> bf16
    gemm_bf16_nt<<<dim3(MS / 128, Hh / 128, 1), 256, GSMEM_TOTAL>>>(
        xb, Dd, 0, wkt, Dd, 0, kb, Hh, 0, bk, nullptr, nullptr, 1.f, Dd, 1);
    // 3) vT = (x @ Wv + bv)^T -> bf16
    gemm_bf16_nt<<<dim3(Hh / 128, MS / 128, 1), 256, GSMEM_TOTAL>>>(
        wvt, Dd, 0, xb, Dd, 0, vTb, MS, 0, nullptr, bv, nullptr, 1.f, Dd, 1);
    // 4-6) fused flash attention -> ctx bf16
    flash_attn<<<dim3(Sq / QB, Bsz), 512, FA_SMEM>>>(qb, kb, vTb, ctxb, inv_sqrt_h);
    // 7) out = ctx @ Wo + bo + x -> fp32
    gemm_bf16_nt<<<dim3(MS / 128, Dd / 128, 1), 256, GSMEM_TOTAL>>>(
        ctxb, Hh, 0, wot, Hh, 0, out, Dd, 0, bo, nullptr, x, 1.f, Hh, 0);
}

// round 8
// speedup vs baseline: 1.2462x; 1.2462x over previous
#include <cuda_runtime.h>
#include <cuda_bf16.h>
#include <cstdint>
#include <math.h>

// Shapes (fixed)
#define Bsz 8
#define Sq  2048
#define Dd  512
#define Hh  512
#define MS  (Bsz * Sq)   // 16384

// ---------------- scratch (device globals) ----------------
__device__ __nv_bfloat16 g_xb  [(long)MS * Dd];
__device__ __nv_bfloat16 g_qb  [(long)MS * Hh];
__device__ __nv_bfloat16 g_kb  [(long)MS * Hh];
__device__ __nv_bfloat16 g_vTb [(long)MS * Hh];     // [Hh, MS]
__device__ __nv_bfloat16 g_ctxb[(long)MS * Hh];
__device__ __nv_bfloat16 g_p   [(long)Bsz * Sq * Sq]; // unnormalized probs (bf16)
__device__ float         g_lsum[MS];                   // per-row exp sums
__device__ __nv_bfloat16 g_wqt[Dd * Hh];
__device__ __nv_bfloat16 g_wkt[Dd * Hh];
__device__ __nv_bfloat16 g_wvt[Dd * Hh];
__device__ __nv_bfloat16 g_wot[Dd * Hh];

// ---------------- helpers ----------------
__device__ __forceinline__ uint32_t smem_u32(const void* p) {
    uint32_t a;
    asm("{ .reg .u64 t; cvta.to.shared.u64 t, %1; cvt.u32.u64 %0, t; }" : "=r"(a) : "l"(p));
    return a;
}
#define LDSM4(r, a)                                                              \
    asm volatile("ldmatrix.sync.aligned.m8n8.x4.shared.b16 {%0,%1,%2,%3}, [%4];" \
                 : "=r"((r)[0]), "=r"((r)[1]), "=r"((r)[2]), "=r"((r)[3])        \
                 : "r"(a))
__device__ __forceinline__ void mma_bf16(float* c, const uint32_t* a,
                                         uint32_t b0, uint32_t b1) {
    asm volatile(
        "mma.sync.aligned.m16n8k16.row.col.f32.bf16.bf16.f32 "
        "{%0,%1,%2,%3}, {%4,%5,%6,%7}, {%8,%9}, {%0,%1,%2,%3};"
        : "+f"(c[0]), "+f"(c[1]), "+f"(c[2]), "+f"(c[3])
        : "r"(a[0]), "r"(a[1]), "r"(a[2]), "r"(a[3]), "r"(b0), "r"(b1));
}
#define CP_ASYNC(dst, src) \
    asm volatile("cp.async.cg.shared.global [%0], [%1], 16;" :: "r"(dst), "l"(src))
#define CP_COMMIT() asm volatile("cp.async.commit_group;" ::: "memory")
#define CP_WAIT(n)  asm volatile("cp.async.wait_group %0;" :: "n"(n) : "memory")

// ============================================================================
// bf16 NT GEMM with fused epilogues.
// C[M,N] = alpha * A[M,K] @ B[N,K]^T, then one of:
//   - plain (+biasN +biasM +res), fp32 or bf16 out
//   - exp mode (rowsum != 0): C = exp(alpha*S) as bf16, atomic row sums
//   - rowdiv mode: C = acc / rowdiv[row], bf16 out
// BM=BN=128, BK=64, 256 threads, 8 warps 2(m)x4(n), 3-stage cp.async.
// ============================================================================
#define RS 144
#define B_OFF  (128 * RS)
#define STAGE  (256 * RS)
#define NSTAGE 3
#define GSMEM_TOTAL (NSTAGE * STAGE)

__device__ __forceinline__ void stage_load(
    uint32_t sbase, const __nv_bfloat16* __restrict__ A, long lda,
    const __nv_bfloat16* __restrict__ B, long ldb, int m0, int n0, int kt, int t)
{
    const int lrow = t >> 3, lch = t & 7;
#pragma unroll
    for (int i = 0; i < 4; i++) {
        const int row = lrow + i * 32;
        CP_ASYNC(sbase + row * RS + lch * 16,
                 A + (long)(m0 + row) * lda + kt + lch * 8);
    }
#pragma unroll
    for (int i = 0; i < 4; i++) {
        const int row = lrow + i * 32;
        CP_ASYNC(sbase + B_OFF + row * RS + lch * 16,
                 B + (long)(n0 + row) * ldb + kt + lch * 8);
    }
}

__global__ __launch_bounds__(256, 2) void gemm_bf16_nt(
    const __nv_bfloat16* __restrict__ A, long lda, long sA,
    const __nv_bfloat16* __restrict__ B, long ldb, long sB,
    void* __restrict__ Cv, long ldc, long sC,
    const float* __restrict__ biasN, const float* __restrict__ biasM,
    const float* __restrict__ res,
    float* __restrict__ rowsum, const float* __restrict__ rowdiv, long rsStride,
    float alpha, int K, int c_bf16)
{
    extern __shared__ __align__(128) char smem[];
    const uint32_t sb = smem_u32(smem);
    const int t = threadIdx.x;
    const int m0 = blockIdx.x * 128;
    const int n0 = blockIdx.y * 128;

    A += (long)blockIdx.z * sA;
    B += (long)blockIdx.z * sB;
    const float* resz = res ? res + (long)blockIdx.z * sC : nullptr;
    float* rsumz = rowsum ? rowsum + (long)blockIdx.z * rsStride : nullptr;
    const float* rdivz = rowdiv ? rowdiv + (long)blockIdx.z * rsStride : nullptr;

    const int lane = t & 31, w = t >> 5;
    const int wm = w & 1, wn = w >> 1;

    const uint32_t aB = sb + (wm * 64 + (lane & 15)) * RS + (lane >> 4) * 16;
    const uint32_t bB = sb + B_OFF + (wn * 32 + (lane & 15)) * RS + (lane >> 4) * 16;

    float acc[4][4][4];
#pragma unroll
    for (int i = 0; i < 4; i++)
#pragma unroll
        for (int j = 0; j < 4; j++)
#pragma unroll
            for (int r = 0; r < 4; r++) acc[i][j][r] = 0.f;

    const int ktiles = K / 64;
    stage_load(sb, A, lda, B, ldb, m0, n0, 0, t);
    CP_COMMIT();
    if (ktiles > 1) stage_load(sb + STAGE, A, lda, B, ldb, m0, n0, 64, t);
    CP_COMMIT();

    for (int kt = 0; kt < ktiles; kt++) {
        if (kt + 2 < ktiles)
            stage_load(sb + ((kt + 2) % NSTAGE) * STAGE, A, lda, B, ldb,
                       m0, n0, (kt + 2) * 64, t);
        CP_COMMIT();
        CP_WAIT(2);
        __syncthreads();

        const uint32_t so = (kt % NSTAGE) * STAGE;
#pragma unroll
        for (int s = 0; s < 4; s++) {
            uint32_t af[4][4], bf[2][4];
#pragma unroll
            for (int mt = 0; mt < 4; mt++)
                LDSM4(af[mt], aB + so + mt * (16 * RS) + s * 32);
#pragma unroll
            for (int p = 0; p < 2; p++)
                LDSM4(bf[p], bB + so + p * (16 * RS) + s * 32);
#pragma unroll
            for (int mt = 0; mt < 4; mt++)
#pragma unroll
                for (int p = 0; p < 2; p++) {
                    mma_bf16(acc[mt][2 * p + 0], af[mt], bf[p][0], bf[p][2]);
                    mma_bf16(acc[mt][2 * p + 1], af[mt], bf[p][1], bf[p][3]);
                }
        }
        __syncthreads();
    }

    const int gcol0 = (lane & 3) * 2;
    const int grow  = lane >> 2;

    if (rsumz) {
        // exp epilogue: C = exp(alpha * acc) bf16, accumulate row sums
        __nv_bfloat16* C = (__nv_bfloat16*)Cv + (long)blockIdx.z * sC;
#pragma unroll
        for (int mt = 0; mt < 4; mt++) {
            const long row = m0 + wm * 64 + mt * 16 + grow;
            float rs0 = 0.f, rs1 = 0.f;
#pragma unroll
            for (int nt = 0; nt < 4; nt++) {
                const int col = n0 + wn * 32 + nt * 8 + gcol0;
                const float e00 = __expf(acc[mt][nt][0] * alpha);
                const float e01 = __expf(acc[mt][nt][1] * alpha);
                const float e10 = __expf(acc[mt][nt][2] * alpha);
                const float e11 = __expf(acc[mt][nt][3] * alpha);
                rs0 += e00 + e01;
                rs1 += e10 + e11;
                *(__nv_bfloat162*)(C + row * ldc + col) =
                    __float22bfloat162_rn(make_float2(e00, e01));
                *(__nv_bfloat162*)(C + (row + 8) * ldc + col) =
                    __float22bfloat162_rn(make_float2(e10, e11));
            }
            // reduce across the 4 col-lanes (lane&3), then one atomic per row
            rs0 += __shfl_xor_sync(0xffffffffu, rs0, 1);
            rs0 += __shfl_xor_sync(0xffffffffu, rs0, 2);
            rs1 += __shfl_xor_sync(0xffffffffu, rs1, 1);
            rs1 += __shfl_xor_sync(0xffffffffu, rs1, 2);
            if ((lane & 3) == 0) {
                atomicAdd(rsumz + row, rs0);
                atomicAdd(rsumz + row + 8, rs1);
            }
        }
        return;
    }

#pragma unroll
    for (int mt = 0; mt < 4; mt++) {
        const long row = m0 + wm * 64 + mt * 16 + grow;
        const float bm0 = biasM ? biasM[row] : 0.f;
        const float bm1 = biasM ? biasM[row + 8] : 0.f;
        const float iv0 = rdivz ? __fdividef(1.f, rdivz[row]) : 1.f;
        const float iv1 = rdivz ? __fdividef(1.f, rdivz[row + 8]) : 1.f;
#pragma unroll
        for (int nt = 0; nt < 4; nt++) {
            const int col = n0 + wn * 32 + nt * 8 + gcol0;
            float2 v0, v1;
            v0.x = acc[mt][nt][0] * alpha * iv0 + bm0;
            v0.y = acc[mt][nt][1] * alpha * iv0 + bm0;
            v1.x = acc[mt][nt][2] * alpha * iv1 + bm1;
            v1.y = acc[mt][nt][3] * alpha * iv1 + bm1;
            if (biasN) {
                const float2 bb = *(const float2*)(biasN + col);
                v0.x += bb.x; v0.y += bb.y; v1.x += bb.x; v1.y += bb.y;
            }
            if (resz) {
                const float2 r0 = *(const float2*)(resz + row * ldc + col);
                const float2 r1 = *(const float2*)(resz + (row + 8) * ldc + col);
                v0.x += r0.x; v0.y += r0.y; v1.x += r1.x; v1.y += r1.y;
            }
            if (c_bf16) {
                __nv_bfloat16* C = (__nv_bfloat16*)Cv + (long)blockIdx.z * sC;
                *(__nv_bfloat162*)(C + row * ldc + col) = __float22bfloat162_rn(v0);
                *(__nv_bfloat162*)(C + (row + 8) * ldc + col) = __float22bfloat162_rn(v1);
            } else {
                float* C = (float*)Cv + (long)blockIdx.z * sC;
                *(float2*)(C + row * ldc + col) = v0;
                *(float2*)(C + (row + 8) * ldc + col) = v1;
            }
        }
    }
}

// ---------------- 512x512 transpose -> bf16 ----------------
__global__ __launch_bounds__(256) void transpose512(const float* __restrict__ W,
                                                    __nv_bfloat16* __restrict__ Wt)
{
    __shared__ float tile[32][33];
    const int tx = threadIdx.x, ty = threadIdx.y;
    int x = blockIdx.x * 32 + tx;
    int y = blockIdx.y * 32 + ty;
#pragma unroll
    for (int i = 0; i < 4; i++)
        tile[ty + i * 8][tx] = W[(y + i * 8) * 512 + x];
    __syncthreads();
    x = blockIdx.y * 32 + tx;
    y = blockIdx.x * 32 + ty;
#pragma unroll
    for (int i = 0; i < 4; i++)
        Wt[(y + i * 8) * 512 + x] = __float2bfloat16_rn(tile[tx][ty + i * 8]);
}

// ---------------- fp32 -> bf16 bulk convert ----------------
__global__ __launch_bounds__(256) void cvt_bf16(const float* __restrict__ in,
                                                __nv_bfloat16* __restrict__ out, long n4)
{
    const long i = (long)blockIdx.x * blockDim.x + threadIdx.x;
    if (i < n4) {
        float4 v = ((const float4*)in)[i];
        *(__nv_bfloat162*)(out + i * 4)     = __float22bfloat162_rn(make_float2(v.x, v.y));
        *(__nv_bfloat162*)(out + i * 4 + 2) = __float22bfloat162_rn(make_float2(v.z, v.w));
    }
}

// ---------------- zero fp32 buffer ----------------
__global__ __launch_bounds__(256) void zero_f32(float* __restrict__ p, long n)
{
    const long i = (long)blockIdx.x * blockDim.x + threadIdx.x;
    if (i < n) p[i] = 0.f;
}

// ---------------- launch ----------------
extern "C" void kernel_launch(void* const* d_in, const int* in_sizes, int n_in,
                              void* d_out, int out_size)
{
    const float* x  = (const float*)d_in[0];
    const float* Wq = (const float*)d_in[1];
    const float* bq = (const float*)d_in[2];
    const float* Wk = (const float*)d_in[3];
    const float* bk = (const float*)d_in[4];
    const float* Wv = (const float*)d_in[5];
    const float* bv = (const float*)d_in[6];
    const float* Wo = (const float*)d_in[7];
    const float* bo = (const float*)d_in[8];
    float* out = (float*)d_out;

    __nv_bfloat16 *xb, *qb, *kb, *vTb, *ctxb, *pb, *wqt, *wkt, *wvt, *wot;
    float* lsum;
    cudaGetSymbolAddress((void**)&xb,   g_xb);
    cudaGetSymbolAddress((void**)&qb,   g_qb);
    cudaGetSymbolAddress((void**)&kb,   g_kb);
    cudaGetSymbolAddress((void**)&vTb,  g_vTb);
    cudaGetSymbolAddress((void**)&ctxb, g_ctxb);
    cudaGetSymbolAddress((void**)&pb,   g_p);
    cudaGetSymbolAddress((void**)&lsum, g_lsum);
    cudaGetSymbolAddress((void**)&wqt,  g_wqt);
    cudaGetSymbolAddress((void**)&wkt,  g_wkt);
    cudaGetSymbolAddress((void**)&wvt,  g_wvt);
    cudaGetSymbolAddress((void**)&wot,  g_wot);

    static int smem_set = 0;
    if (!smem_set) {
        cudaFuncSetAttribute(gemm_bf16_nt,
                             cudaFuncAttributeMaxDynamicSharedMemorySize, GSMEM_TOTAL);
        smem_set = 1;
    }

    // 0) transpose + convert weights; convert x; zero row sums
    {
        dim3 g(16, 16), b(32, 8);
        transpose512<<<g, b>>>(Wq, wqt);
        transpose512<<<g, b>>>(Wk, wkt);
        transpose512<<<g, b>>>(Wv, wvt);
        transpose512<<<g, b>>>(Wo, wot);
        const long n4 = (long)MS * Dd / 4;
        cvt_bf16<<<(n4 + 255) / 256, 256>>>(x, xb, n4);
        zero_f32<<<(MS + 255) / 256, 256>>>(lsum, MS);
    }

    const float inv_sqrt_h = 1.f / sqrtf((float)Hh);

    // 1) q = x @ Wq (+bq) -> bf16
    gemm_bf16_nt<<<dim3(MS / 128, Hh / 128, 1), 256, GSMEM_TOTAL>>>(
        xb, Dd, 0, wqt, Dd, 0, qb, Hh, 0, bq, nullptr, nullptr,
        nullptr, nullptr, 0, 1.f, Dd, 1);
    // 2) k -> bf16
    gemm_bf16_nt<<<dim3(MS / 128, Hh / 128, 1), 256, GSMEM_TOTAL>>>(
        xb, Dd, 0, wkt, Dd, 0, kb, Hh, 0, bk, nullptr, nullptr,
        nullptr, nullptr, 0, 1.f, Dd, 1);
    // 3) vT = (x @ Wv + bv)^T -> bf16
    gemm_bf16_nt<<<dim3(Hh / 128, MS / 128, 1), 256, GSMEM_TOTAL>>>(
        wvt, Dd, 0, xb, Dd, 0, vTb, MS, 0, nullptr, bv, nullptr,
        nullptr, nullptr, 0, 1.f, Dd, 1);
    // 4) P_unnorm = exp(q @ k^T / sqrt(H)) -> bf16, row sums -> lsum
    gemm_bf16_nt<<<dim3(Sq / 128, Sq / 128, Bsz), 256, GSMEM_TOTAL>>>(
        qb, Hh, (long)Sq * Hh, kb, Hh, (long)Sq * Hh, pb, Sq, (long)Sq * Sq,
        nullptr, nullptr, nullptr, lsum, nullptr, Sq, inv_sqrt_h, Hh, 1);
    // 5) ctx = (P_unnorm @ V) / lsum -> bf16
    gemm_bf16_nt<<<dim3(Sq / 128, Hh / 128, Bsz), 256, GSMEM_TOTAL>>>(
        pb, Sq, (long)Sq * Sq, vTb, MS, Sq, ctxb, Hh, (long)Sq * Hh,
        nullptr, nullptr, nullptr, nullptr, lsum, Sq, 1.f, Sq, 1);
    // 6) out = ctx @ Wo + bo + x -> fp32
    gemm_bf16_nt<<<dim3(MS / 128, Dd / 128, 1), 256, GSMEM_TOTAL>>>(
        ctxb, Hh, 0, wot, Hh, 0, out, Dd, 0, bo, nullptr, x,
        nullptr, nullptr, 0, 1.f, Hh, 0);
}

// round 9
// speedup vs baseline: 1.3617x; 1.0927x over previous
#include <cuda_runtime.h>
#include <cuda_bf16.h>
#include <cstdint>
#include <math.h>

// Shapes (fixed)
#define Bsz 8
#define Sq  2048
#define Dd  512
#define Hh  512
#define MS  (Bsz * Sq)   // 16384

// ---------------- scratch (device globals) ----------------
__device__ __nv_bfloat16 g_xb  [(long)MS * Dd];
__device__ __nv_bfloat16 g_qb  [(long)MS * Hh];
__device__ __nv_bfloat16 g_kb  [(long)MS * Hh];
__device__ __nv_bfloat16 g_vTb [(long)MS * Hh];     // [Hh, MS]
__device__ __nv_bfloat16 g_ctxb[(long)MS * Hh];
__device__ __nv_bfloat16 g_p   [(long)Bsz * Sq * Sq]; // unnormalized probs (bf16)
__device__ float         g_lsum[MS];                   // per-row exp sums
__device__ __nv_bfloat16 g_wqt[Dd * Hh];
__device__ __nv_bfloat16 g_wkt[Dd * Hh];
__device__ __nv_bfloat16 g_wvt[Dd * Hh];
__device__ __nv_bfloat16 g_wot[Dd * Hh];

// ---------------- helpers ----------------
__device__ __forceinline__ uint32_t smem_u32(const void* p) {
    uint32_t a;
    asm("{ .reg .u64 t; cvta.to.shared.u64 t, %1; cvt.u32.u64 %0, t; }" : "=r"(a) : "l"(p));
    return a;
}
#define LDSM4(r, a)                                                              \
    asm volatile("ldmatrix.sync.aligned.m8n8.x4.shared.b16 {%0,%1,%2,%3}, [%4];" \
                 : "=r"((r)[0]), "=r"((r)[1]), "=r"((r)[2]), "=r"((r)[3])        \
                 : "r"(a))
__device__ __forceinline__ void mma_bf16(float* c, const uint32_t* a,
                                         uint32_t b0, uint32_t b1) {
    asm volatile(
        "mma.sync.aligned.m16n8k16.row.col.f32.bf16.bf16.f32 "
        "{%0,%1,%2,%3}, {%4,%5,%6,%7}, {%8,%9}, {%0,%1,%2,%3};"
        : "+f"(c[0]), "+f"(c[1]), "+f"(c[2]), "+f"(c[3])
        : "r"(a[0]), "r"(a[1]), "r"(a[2]), "r"(a[3]), "r"(b0), "r"(b1));
}
#define CP_ASYNC(dst, src) \
    asm volatile("cp.async.cg.shared.global [%0], [%1], 16;" :: "r"(dst), "l"(src))
#define CP_COMMIT() asm volatile("cp.async.commit_group;" ::: "memory")
#define CP_WAIT(n)  asm volatile("cp.async.wait_group %0;" :: "n"(n) : "memory")

// ============================================================================
// bf16 NT GEMM with fused epilogues (single-barrier 3-stage pipeline).
// ============================================================================
#define RS 144
#define B_OFF  (128 * RS)
#define STAGE  (256 * RS)
#define NSTAGE 3
#define GSMEM_TOTAL (NSTAGE * STAGE)

__device__ __forceinline__ void stage_load(
    uint32_t sbase, const __nv_bfloat16* __restrict__ A, long lda,
    const __nv_bfloat16* __restrict__ B, long ldb, int m0, int n0, int kt, int t)
{
    const int lrow = t >> 3, lch = t & 7;
#pragma unroll
    for (int i = 0; i < 4; i++) {
        const int row = lrow + i * 32;
        CP_ASYNC(sbase + row * RS + lch * 16,
                 A + (long)(m0 + row) * lda + kt + lch * 8);
    }
#pragma unroll
    for (int i = 0; i < 4; i++) {
        const int row = lrow + i * 32;
        CP_ASYNC(sbase + B_OFF + row * RS + lch * 16,
                 B + (long)(n0 + row) * ldb + kt + lch * 8);
    }
}

__global__ __launch_bounds__(256, 2) void gemm_bf16_nt(
    const __nv_bfloat16* __restrict__ A, long lda, long sA,
    const __nv_bfloat16* __restrict__ B, long ldb, long sB,
    void* __restrict__ Cv, long ldc, long sC,
    const float* __restrict__ biasN, const float* __restrict__ biasM,
    const float* __restrict__ res,
    float* __restrict__ rowsum, const float* __restrict__ rowdiv, long rsStride,
    float alpha, int K, int c_bf16)
{
    extern __shared__ __align__(128) char smem[];
    const uint32_t sb = smem_u32(smem);
    const int t = threadIdx.x;
    const int m0 = blockIdx.x * 128;
    const int n0 = blockIdx.y * 128;

    A += (long)blockIdx.z * sA;
    B += (long)blockIdx.z * sB;
    const float* resz = res ? res + (long)blockIdx.z * sC : nullptr;
    float* rsumz = rowsum ? rowsum + (long)blockIdx.z * rsStride : nullptr;
    const float* rdivz = rowdiv ? rowdiv + (long)blockIdx.z * rsStride : nullptr;

    const int lane = t & 31, w = t >> 5;
    const int wm = w & 1, wn = w >> 1;

    const uint32_t aB = sb + (wm * 64 + (lane & 15)) * RS + (lane >> 4) * 16;
    const uint32_t bB = sb + B_OFF + (wn * 32 + (lane & 15)) * RS + (lane >> 4) * 16;

    float acc[4][4][4];
#pragma unroll
    for (int i = 0; i < 4; i++)
#pragma unroll
        for (int j = 0; j < 4; j++)
#pragma unroll
            for (int r = 0; r < 4; r++) acc[i][j][r] = 0.f;

    const int ktiles = K / 64;
    // prologue: stages 0, 1
    stage_load(sb, A, lda, B, ldb, m0, n0, 0, t);
    CP_COMMIT();
    if (ktiles > 1) stage_load(sb + STAGE, A, lda, B, ldb, m0, n0, 64, t);
    CP_COMMIT();
    CP_WAIT(1);            // stage 0 complete
    __syncthreads();

    for (int kt = 0; kt < ktiles; kt++) {
        // copy stage kt+2 into buffer (kt+2)%3 = (kt-1)%3 — all warps finished
        // reading it (barrier at end of iter kt-1).
        if (kt + 2 < ktiles)
            stage_load(sb + ((kt + 2) % NSTAGE) * STAGE, A, lda, B, ldb,
                       m0, n0, (kt + 2) * 64, t);
        CP_COMMIT();

        // MMA on stage kt (complete per previous iteration's wait+barrier)
        const uint32_t so = (kt % NSTAGE) * STAGE;
#pragma unroll
        for (int s = 0; s < 4; s++) {
            uint32_t af[4][4], bf[2][4];
#pragma unroll
            for (int mt = 0; mt < 4; mt++)
                LDSM4(af[mt], aB + so + mt * (16 * RS) + s * 32);
#pragma unroll
            for (int p = 0; p < 2; p++)
                LDSM4(bf[p], bB + so + p * (16 * RS) + s * 32);
#pragma unroll
            for (int mt = 0; mt < 4; mt++)
#pragma unroll
                for (int p = 0; p < 2; p++) {
                    mma_bf16(acc[mt][2 * p + 0], af[mt], bf[p][0], bf[p][2]);
                    mma_bf16(acc[mt][2 * p + 1], af[mt], bf[p][1], bf[p][3]);
                }
        }

        CP_WAIT(1);        // stage kt+1 complete (only newest group pending)
        __syncthreads();   // all warps done reading stage kt
    }

    const int gcol0 = (lane & 3) * 2;
    const int grow  = lane >> 2;

    if (rsumz) {
        // exp epilogue: C = exp(alpha * acc) bf16, accumulate row sums
        __nv_bfloat16* C = (__nv_bfloat16*)Cv + (long)blockIdx.z * sC;
#pragma unroll
        for (int mt = 0; mt < 4; mt++) {
            const long row = m0 + wm * 64 + mt * 16 + grow;
            float rs0 = 0.f, rs1 = 0.f;
#pragma unroll
            for (int nt = 0; nt < 4; nt++) {
                const int col = n0 + wn * 32 + nt * 8 + gcol0;
                const float e00 = __expf(acc[mt][nt][0] * alpha);
                const float e01 = __expf(acc[mt][nt][1] * alpha);
                const float e10 = __expf(acc[mt][nt][2] * alpha);
                const float e11 = __expf(acc[mt][nt][3] * alpha);
                rs0 += e00 + e01;
                rs1 += e10 + e11;
                *(__nv_bfloat162*)(C + row * ldc + col) =
                    __float22bfloat162_rn(make_float2(e00, e01));
                *(__nv_bfloat162*)(C + (row + 8) * ldc + col) =
                    __float22bfloat162_rn(make_float2(e10, e11));
            }
            rs0 += __shfl_xor_sync(0xffffffffu, rs0, 1);
            rs0 += __shfl_xor_sync(0xffffffffu, rs0, 2);
            rs1 += __shfl_xor_sync(0xffffffffu, rs1, 1);
            rs1 += __shfl_xor_sync(0xffffffffu, rs1, 2);
            if ((lane & 3) == 0) {
                atomicAdd(rsumz + row, rs0);
                atomicAdd(rsumz + row + 8, rs1);
            }
        }
        return;
    }

#pragma unroll
    for (int mt = 0; mt < 4; mt++) {
        const long row = m0 + wm * 64 + mt * 16 + grow;
        const float bm0 = biasM ? biasM[row] : 0.f;
        const float bm1 = biasM ? biasM[row + 8] : 0.f;
        const float iv0 = rdivz ? __fdividef(1.f, rdivz[row]) : 1.f;
        const float iv1 = rdivz ? __fdividef(1.f, rdivz[row + 8]) : 1.f;
#pragma unroll
        for (int nt = 0; nt < 4; nt++) {
            const int col = n0 + wn * 32 + nt * 8 + gcol0;
            float2 v0, v1;
            v0.x = acc[mt][nt][0] * alpha * iv0 + bm0;
            v0.y = acc[mt][nt][1] * alpha * iv0 + bm0;
            v1.x = acc[mt][nt][2] * alpha * iv1 + bm1;
            v1.y = acc[mt][nt][3] * alpha * iv1 + bm1;
            if (biasN) {
                const float2 bb = *(const float2*)(biasN + col);
                v0.x += bb.x; v0.y += bb.y; v1.x += bb.x; v1.y += bb.y;
            }
            if (resz) {
                const float2 r0 = *(const float2*)(resz + row * ldc + col);
                const float2 r1 = *(const float2*)(resz + (row + 8) * ldc + col);
                v0.x += r0.x; v0.y += r0.y; v1.x += r1.x; v1.y += r1.y;
            }
            if (c_bf16) {
                __nv_bfloat16* C = (__nv_bfloat16*)Cv + (long)blockIdx.z * sC;
                *(__nv_bfloat162*)(C + row * ldc + col) = __float22bfloat162_rn(v0);
                *(__nv_bfloat162*)(C + (row + 8) * ldc + col) = __float22bfloat162_rn(v1);
            } else {
                float* C = (float*)Cv + (long)blockIdx.z * sC;
                *(float2*)(C + row * ldc + col) = v0;
                *(float2*)(C + (row + 8) * ldc + col) = v1;
            }
        }
    }
}

// ---------------- 4x 512x512 transpose -> bf16, one launch ----------------
struct TPtrs {
    const float* w[4];
    __nv_bfloat16* wt[4];
};
__global__ __launch_bounds__(256) void transpose_all(TPtrs p)
{
    const float* W = p.w[blockIdx.z];
    __nv_bfloat16* Wt = p.wt[blockIdx.z];
    __shared__ float tile[32][33];
    const int tx = threadIdx.x, ty = threadIdx.y;
    int x = blockIdx.x * 32 + tx;
    int y = blockIdx.y * 32 + ty;
#pragma unroll
    for (int i = 0; i < 4; i++)
        tile[ty + i * 8][tx] = W[(y + i * 8) * 512 + x];
    __syncthreads();
    x = blockIdx.y * 32 + tx;
    y = blockIdx.x * 32 + ty;
#pragma unroll
    for (int i = 0; i < 4; i++)
        Wt[(y + i * 8) * 512 + x] = __float2bfloat16_rn(tile[tx][ty + i * 8]);
}

// ---------------- fp32 -> bf16 bulk convert (+ zero lsum) ----------------
__global__ __launch_bounds__(256) void cvt_bf16(const float* __restrict__ in,
                                                __nv_bfloat16* __restrict__ out,
                                                long n4, float* __restrict__ zbuf,
                                                long zn)
{
    const long i = (long)blockIdx.x * blockDim.x + threadIdx.x;
    if (i < n4) {
        float4 v = ((const float4*)in)[i];
        *(__nv_bfloat162*)(out + i * 4)     = __float22bfloat162_rn(make_float2(v.x, v.y));
        *(__nv_bfloat162*)(out + i * 4 + 2) = __float22bfloat162_rn(make_float2(v.z, v.w));
    }
    if (i < zn) zbuf[i] = 0.f;
}

// ---------------- launch ----------------
extern "C" void kernel_launch(void* const* d_in, const int* in_sizes, int n_in,
                              void* d_out, int out_size)
{
    const float* x  = (const float*)d_in[0];
    const float* Wq = (const float*)d_in[1];
    const float* bq = (const float*)d_in[2];
    const float* Wk = (const float*)d_in[3];
    const float* bk = (const float*)d_in[4];
    const float* Wv = (const float*)d_in[5];
    const float* bv = (const float*)d_in[6];
    const float* Wo = (const float*)d_in[7];
    const float* bo = (const float*)d_in[8];
    float* out = (float*)d_out;

    __nv_bfloat16 *xb, *qb, *kb, *vTb, *ctxb, *pb, *wqt, *wkt, *wvt, *wot;
    float* lsum;
    cudaGetSymbolAddress((void**)&xb,   g_xb);
    cudaGetSymbolAddress((void**)&qb,   g_qb);
    cudaGetSymbolAddress((void**)&kb,   g_kb);
    cudaGetSymbolAddress((void**)&vTb,  g_vTb);
    cudaGetSymbolAddress((void**)&ctxb, g_ctxb);
    cudaGetSymbolAddress((void**)&pb,   g_p);
    cudaGetSymbolAddress((void**)&lsum, g_lsum);
    cudaGetSymbolAddress((void**)&wqt,  g_wqt);
    cudaGetSymbolAddress((void**)&wkt,  g_wkt);
    cudaGetSymbolAddress((void**)&wvt,  g_wvt);
    cudaGetSymbolAddress((void**)&wot,  g_wot);

    static cudaStream_t s1 = nullptr, s2 = nullptr;
    static cudaEvent_t ev0, ev1, ev2;
    if (!s1) {
        cudaFuncSetAttribute(gemm_bf16_nt,
                             cudaFuncAttributeMaxDynamicSharedMemorySize, GSMEM_TOTAL);
        cudaStreamCreateWithFlags(&s1, cudaStreamNonBlocking);
        cudaStreamCreateWithFlags(&s2, cudaStreamNonBlocking);
        cudaEventCreateWithFlags(&ev0, cudaEventDisableTiming);
        cudaEventCreateWithFlags(&ev1, cudaEventDisableTiming);
        cudaEventCreateWithFlags(&ev2, cudaEventDisableTiming);
    }

    // 0) transpose + convert weights; convert x; zero row sums
    {
        TPtrs tp;
        tp.w[0] = Wq; tp.w[1] = Wk; tp.w[2] = Wv; tp.w[3] = Wo;
        tp.wt[0] = wqt; tp.wt[1] = wkt; tp.wt[2] = wvt; tp.wt[3] = wot;
        transpose_all<<<dim3(16, 16, 4), dim3(32, 8)>>>(tp);
        const long n4 = (long)MS * Dd / 4;
        cvt_bf16<<<(n4 + 255) / 256, 256>>>(x, xb, n4, lsum, MS);
    }

    const float inv_sqrt_h = 1.f / sqrtf((float)Hh);

    // fork: q on stream 0, k on s1, vT on s2 (all depend on transpose+cvt)
    cudaEventRecord(ev0, 0);
    cudaStreamWaitEvent(s1, ev0, 0);
    cudaStreamWaitEvent(s2, ev0, 0);

    // 1) q = x @ Wq (+bq) -> bf16    [stream 0]
    gemm_bf16_nt<<<dim3(MS / 128, Hh / 128, 1), 256, GSMEM_TOTAL>>>(
        xb, Dd, 0, wqt, Dd, 0, qb, Hh, 0, bq, nullptr, nullptr,
        nullptr, nullptr, 0, 1.f, Dd, 1);
    // 2) k -> bf16                    [s1]
    gemm_bf16_nt<<<dim3(MS / 128, Hh / 128, 1), 256, GSMEM_TOTAL, s1>>>(
        xb, Dd, 0, wkt, Dd, 0, kb, Hh, 0, bk, nullptr, nullptr,
        nullptr, nullptr, 0, 1.f, Dd, 1);
    // 3) vT = (x @ Wv + bv)^T -> bf16 [s2]
    gemm_bf16_nt<<<dim3(Hh / 128, MS / 128, 1), 256, GSMEM_TOTAL, s2>>>(
        wvt, Dd, 0, xb, Dd, 0, vTb, MS, 0, nullptr, bv, nullptr,
        nullptr, nullptr, 0, 1.f, Dd, 1);

    cudaEventRecord(ev1, s1);
    cudaEventRecord(ev2, s2);

    // 4) scores: needs q (stream 0) + k (ev1)
    cudaStreamWaitEvent(0, ev1, 0);
    gemm_bf16_nt<<<dim3(Sq / 128, Sq / 128, Bsz), 256, GSMEM_TOTAL>>>(
        qb, Hh, (long)Sq * Hh, kb, Hh, (long)Sq * Hh, pb, Sq, (long)Sq * Sq,
        nullptr, nullptr, nullptr, lsum, nullptr, Sq, inv_sqrt_h, Hh, 1);

    // 5) ctx = (P_unnorm @ V) / lsum -> bf16 (needs vT: ev2)
    cudaStreamWaitEvent(0, ev2, 0);
    gemm_bf16_nt<<<dim3(Sq / 128, Hh / 128, Bsz), 256, GSMEM_TOTAL>>>(
        pb, Sq, (long)Sq * Sq, vTb, MS, Sq, ctxb, Hh, (long)Sq * Hh,
        nullptr, nullptr, nullptr, nullptr, lsum, Sq, 1.f, Sq, 1);

    // 6) out = ctx @ Wo + bo + x -> fp32
    gemm_bf16_nt<<<dim3(MS / 128, Dd / 128, 1), 256, GSMEM_TOTAL>>>(
        ctxb, Hh, 0, wot, Hh, 0, out, Dd, 0, bo, nullptr, x,
        nullptr, nullptr, 0, 1.f, Hh, 0);
}